// round 2
// baseline (speedup 1.0000x reference)
#include <cuda_runtime.h>
#include <math.h>

#define NB 4
#define C_ 256
#define H_ 64
#define W_ 64
#define G_ 8
#define CG_ 32
#define P_ 9
#define HW_ (H_*W_)
#define M_ (C_*H_*W_)

// scratch (device globals; no allocation allowed)
__device__ float g_x1[NB*HW_*C_];      // NHWC conv+bias result
__device__ float g_xn[NB*HW_*C_];      // NHWC original x
__device__ float g_part[NB*1024*2];    // per-block partial sums (sum, sumsq)
__device__ float g_ms[NB*2];           // per-sample mean, rstd

__device__ __forceinline__ float gelu_exact(float v) {
    return 0.5f * v * (1.0f + erff(v * 0.70710678118654752f));
}

// ---------------------------------------------------------------------------
// K1: depthwise 3x3 conv (+bias) NCHW -> NHWC, transpose x -> NHWC,
//     per-block partial sums for GroupNorm stats.
// grid: (W/32, C/32, N*H), block: (32, 8)
// ---------------------------------------------------------------------------
__global__ __launch_bounds__(256) void k_conv(const float* __restrict__ x,
                                              const float* __restrict__ dww,
                                              const float* __restrict__ dwb) {
    int wt = blockIdx.x, ct = blockIdx.y, nh = blockIdx.z;
    int n = nh >> 6, h = nh & 63;
    int w = wt * 32 + threadIdx.x;
    int c0 = ct * 32;

    __shared__ float t1[32][33];
    __shared__ float t0[32][33];
    __shared__ float rs[256];
    __shared__ float rq[256];

    float s1 = 0.f, s2 = 0.f;

    #pragma unroll
    for (int i = 0; i < 4; i++) {
        int cl = threadIdx.y * 4 + i;
        int c = c0 + cl;
        const float* xp = x + ((size_t)(n * C_ + c) * H_) * W_;
        float wgt[9];
        #pragma unroll
        for (int k = 0; k < 9; k++) wgt[k] = dww[c * 9 + k];
        float acc = dwb[c];
        float center = 0.f;
        #pragma unroll
        for (int dy = 0; dy < 3; dy++) {
            int hy = h + dy - 1;
            if (hy < 0 || hy >= H_) continue;
            #pragma unroll
            for (int dx = 0; dx < 3; dx++) {
                int wx = w + dx - 1;
                if (wx < 0 || wx >= W_) continue;
                float v = __ldg(xp + hy * W_ + wx);
                acc = fmaf(wgt[dy * 3 + dx], v, acc);
                if (dy == 1 && dx == 1) center = v;
            }
        }
        t1[cl][threadIdx.x] = acc;
        t0[cl][threadIdx.x] = center;
        s1 += acc;
        s2 += acc * acc;
    }

    int t = threadIdx.y * 32 + threadIdx.x;
    rs[t] = s1; rq[t] = s2;
    __syncthreads();
    #pragma unroll
    for (int s = 128; s > 0; s >>= 1) {
        if (t < s) { rs[t] += rs[t + s]; rq[t] += rq[t + s]; }
        __syncthreads();
    }
    if (t == 0) {
        int pid = (h * 2 + wt) * 8 + ct;   // 1024 blocks per sample
        g_part[(n * 1024 + pid) * 2 + 0] = rs[0];
        g_part[(n * 1024 + pid) * 2 + 1] = rq[0];
    }

    // coalesced NHWC writes (thread.x now indexes channel)
    #pragma unroll
    for (int i = 0; i < 4; i++) {
        int ww = threadIdx.y + 8 * i;
        size_t pix = (size_t)(n * H_ + h) * W_ + wt * 32 + ww;
        g_x1[pix * C_ + c0 + threadIdx.x] = t1[threadIdx.x][ww];
        g_xn[pix * C_ + c0 + threadIdx.x] = t0[threadIdx.x][ww];
    }
}

// ---------------------------------------------------------------------------
// K2: finalize per-sample mean / rstd (deterministic tree reduce)
// grid: NB blocks, 256 threads
// ---------------------------------------------------------------------------
__global__ void k_stats() {
    int n = blockIdx.x;
    int t = threadIdx.x;
    float s1 = 0.f, s2 = 0.f;
    for (int i = t; i < 1024; i += 256) {
        s1 += g_part[(n * 1024 + i) * 2 + 0];
        s2 += g_part[(n * 1024 + i) * 2 + 1];
    }
    __shared__ float rs[256];
    __shared__ float rq[256];
    rs[t] = s1; rq[t] = s2;
    __syncthreads();
    #pragma unroll
    for (int s = 128; s > 0; s >>= 1) {
        if (t < s) { rs[t] += rs[t + s]; rq[t] += rq[t + s]; }
        __syncthreads();
    }
    if (t == 0) {
        float mu = rs[0] / (float)M_;
        float var = rq[0] / (float)M_ - mu * mu;
        g_ms[n * 2 + 0] = mu;
        g_ms[n * 2 + 1] = rsqrtf(var + 1e-5f);
    }
}

// ---------------------------------------------------------------------------
// K3: fused GN + GELU + projection GEMM + softmax + deformable sampling.
// grid: (W/32, H, N), block: 256 threads. One block = 32-pixel row tile.
// dynamic smem: Ys[256][36] (activations, later reused as output staging
//               Obuf[256][33]) and O[216][33] (GEMM results).
// ---------------------------------------------------------------------------
#define YS_FLOATS (256 * 36)
#define O_FLOATS  (216 * 33)
#define SMEM_BYTES ((YS_FLOATS + O_FLOATS) * 4)

__global__ __launch_bounds__(256) void k_main(const float* __restrict__ gng,
                                              const float* __restrict__ gnb,
                                              const float* __restrict__ offw,
                                              const float* __restrict__ offb,
                                              const float* __restrict__ maskw,
                                              const float* __restrict__ maskb,
                                              float* __restrict__ out) {
    extern __shared__ __align__(16) float sm[];
    float* Ys = sm;                 // [256][36]
    float* O  = sm + YS_FLOATS;     // [216][33]

    int wt = blockIdx.x, h = blockIdx.y, n = blockIdx.z;
    int w0 = wt * 32;
    int t = threadIdx.x;
    int lane = t & 31;
    int wid = t >> 5;

    float mu = g_ms[n * 2 + 0];
    float rstd = g_ms[n * 2 + 1];

    // ---- Phase A: load x1 tile, apply GN + GELU, store to Ys[c][pix] ----
    size_t pixbase = (size_t)(n * H_ + h) * W_ + w0;
    #pragma unroll
    for (int q = 0; q < 4; q++) {
        int pix = wid * 4 + q;
        const float* src = g_x1 + (pixbase + pix) * C_;
        #pragma unroll
        for (int half = 0; half < 2; half++) {
            int c = lane * 4 + half * 128;
            float4 v  = *(const float4*)(src + c);
            float4 gg = *(const float4*)(gng + c);
            float4 bb = *(const float4*)(gnb + c);
            Ys[(c + 0) * 36 + pix] = gelu_exact(fmaf((v.x - mu) * rstd, gg.x, bb.x));
            Ys[(c + 1) * 36 + pix] = gelu_exact(fmaf((v.y - mu) * rstd, gg.y, bb.y));
            Ys[(c + 2) * 36 + pix] = gelu_exact(fmaf((v.z - mu) * rstd, gg.z, bb.z));
            Ys[(c + 3) * 36 + pix] = gelu_exact(fmaf((v.w - mu) * rstd, gg.w, bb.w));
        }
    }
    __syncthreads();

    // ---- Phase B: GEMM  O[216][32] = W^T(216x256) @ Ys(256x32) + bias ----
    // thread t<216: 4 outputs (j) x 8 pixels register tile
    if (t < 216) {
        int jt = t >> 2, pt = t & 3;
        int j0 = jt * 4;
        const float* wb;
        const float* bptr;
        int stride;
        if (j0 < 144) { wb = offw + j0; bptr = offb + j0; stride = 144; }
        else          { wb = maskw + (j0 - 144); bptr = maskb + (j0 - 144); stride = 72; }

        float acc[32];
        #pragma unroll
        for (int jj = 0; jj < 4; jj++) {
            float b = bptr[jj];
            #pragma unroll
            for (int pp = 0; pp < 8; pp++) acc[jj * 8 + pp] = b;
        }

        const float* yc = Ys + pt * 8;
        for (int c = 0; c < 256; c++) {
            float4 wv = *(const float4*)(wb + c * stride);
            float4 ya = *(const float4*)(yc);
            float4 yb = *(const float4*)(yc + 4);
            float wr[4] = {wv.x, wv.y, wv.z, wv.w};
            float yr[8] = {ya.x, ya.y, ya.z, ya.w, yb.x, yb.y, yb.z, yb.w};
            #pragma unroll
            for (int jj = 0; jj < 4; jj++)
                #pragma unroll
                for (int pp = 0; pp < 8; pp++)
                    acc[jj * 8 + pp] = fmaf(wr[jj], yr[pp], acc[jj * 8 + pp]);
            yc += 36;
        }

        #pragma unroll
        for (int jj = 0; jj < 4; jj++)
            #pragma unroll
            for (int pp = 0; pp < 8; pp++)
                O[(j0 + jj) * 33 + pt * 8 + pp] = acc[jj * 8 + pp];
    }
    __syncthreads();

    // ---- Phase C: softmax over P + deformable bilinear gather ----
    // warp wid owns group g = wid; lanes span the 32 group-channels so each
    // corner gather is one contiguous 128B load. Results staged in smem
    // (reusing Ys) so final NCHW stores are coalesced.
    float* Obuf = Ys;   // [256][33] fits in Ys space (8448 <= 9216 floats)
    int g = wid;
    const float* xbase = g_xn + (size_t)n * HW_ * C_ + g * CG_ + lane;

    for (int pix = 0; pix < 32; pix++) {
        // softmax over the 9 mask logits (uniform per warp; redundant per lane)
        float ml[9];
        float mx = -1e30f;
        #pragma unroll
        for (int p = 0; p < P_; p++) {
            ml[p] = O[(144 + g * P_ + p) * 33 + pix];
            mx = fmaxf(mx, ml[p]);
        }
        float s = 0.f;
        #pragma unroll
        for (int p = 0; p < P_; p++) { ml[p] = expf(ml[p] - mx); s += ml[p]; }
        float inv = 1.f / s;

        float acc = 0.f;
        float wpixf = (float)(w0 + pix);
        float hf = (float)h;
        #pragma unroll
        for (int p = 0; p < P_; p++) {
            float ox = O[((g * P_ + p) * 2 + 0) * 33 + pix];
            float oy = O[((g * P_ + p) * 2 + 1) * 33 + pix];
            float fx = wpixf + (float)(p / 3 - 1) + ox;   // unpadded coords
            float fy = hf    + (float)(p % 3 - 1) + oy;
            fx = fminf(fmaxf(fx, -2.f), (float)(W_ + 1));
            fy = fminf(fmaxf(fy, -2.f), (float)(H_ + 1));
            float x0f = floorf(fx), y0f = floorf(fy);
            float wxf = fx - x0f, wyf = fy - y0f;
            int ix = (int)x0f, iy = (int)y0f;
            float m = ml[p] * inv;
            float w00 = m * (1.f - wyf) * (1.f - wxf);
            float w01 = m * (1.f - wyf) * wxf;
            float w10 = m * wyf * (1.f - wxf);
            float w11 = m * wyf * wxf;
            bool vx0 = (ix >= 0) && (ix < W_);
            bool vx1 = (ix + 1 >= 0) && (ix + 1 < W_);
            bool vy0 = (iy >= 0) && (iy < H_);
            bool vy1 = (iy + 1 >= 0) && (iy + 1 < H_);
            const float* rp = xbase + ((size_t)iy * W_ + ix) * C_;
            if (vy0 && vx0) acc = fmaf(w00, __ldg(rp), acc);
            if (vy0 && vx1) acc = fmaf(w01, __ldg(rp + C_), acc);
            if (vy1 && vx0) acc = fmaf(w10, __ldg(rp + W_ * C_), acc);
            if (vy1 && vx1) acc = fmaf(w11, __ldg(rp + W_ * C_ + C_), acc);
        }
        Obuf[(g * CG_ + lane) * 33 + pix] = acc;
    }
    __syncthreads();

    // ---- Phase D: coalesced NCHW store ----
    #pragma unroll
    for (int i = 0; i < 32; i++) {
        int c = wid * 32 + i;
        out[((size_t)(n * C_ + c) * H_ + h) * W_ + w0 + lane] = Obuf[c * 33 + lane];
    }
}

// ---------------------------------------------------------------------------
extern "C" void kernel_launch(void* const* d_in, const int* in_sizes, int n_in,
                              void* d_out, int out_size) {
    const float* x     = (const float*)d_in[0];
    const float* dw_w  = (const float*)d_in[1];
    const float* dw_b  = (const float*)d_in[2];
    const float* gn_g  = (const float*)d_in[3];
    const float* gn_b  = (const float*)d_in[4];
    const float* off_w = (const float*)d_in[5];
    const float* off_b = (const float*)d_in[6];
    const float* mask_w= (const float*)d_in[7];
    const float* mask_b= (const float*)d_in[8];
    float* out = (float*)d_out;

    cudaFuncSetAttribute(k_main, cudaFuncAttributeMaxDynamicSharedMemorySize, SMEM_BYTES);

    dim3 g1(W_ / 32, C_ / 32, NB * H_);
    dim3 b1(32, 8);
    k_conv<<<g1, b1>>>(x, dw_w, dw_b);
    k_stats<<<NB, 256>>>();
    dim3 g3(W_ / 32, H_, NB);
    k_main<<<g3, 256, SMEM_BYTES>>>(gn_g, gn_b, off_w, off_b, mask_w, mask_b, out);
}

// round 3
// speedup vs baseline: 1.0283x; 1.0283x over previous
#include <cuda_runtime.h>
#include <math.h>

#define NB 4
#define C_ 256
#define H_ 64
#define W_ 64
#define G_ 8
#define CG_ 32
#define P_ 9
#define HW_ (H_*W_)
#define M_ (C_*H_*W_)

// scratch (device globals; no allocation allowed)
__device__ float g_x1[NB*HW_*C_];      // NHWC conv+bias result
__device__ float g_xn[NB*HW_*C_];      // NHWC original x
__device__ float g_part[NB*1024*2];    // per-block partial sums (sum, sumsq)
__device__ float g_ms[NB*2];           // per-sample mean, rstd

__device__ __forceinline__ float gelu_exact(float v) {
    return 0.5f * v * (1.0f + erff(v * 0.70710678118654752f));
}

// ---- f32x2 packed-FMA helpers (FFMA2 — only reachable via PTX) ----
typedef unsigned long long ull;
__device__ __forceinline__ ull pack2(float lo, float hi) {
    ull r; asm("mov.b64 %0, {%1, %2};" : "=l"(r) : "f"(lo), "f"(hi)); return r;
}
__device__ __forceinline__ ull dup2(float v) {
    ull r; asm("mov.b64 %0, {%1, %1};" : "=l"(r) : "f"(v)); return r;
}
__device__ __forceinline__ void fma2(ull& d, ull a, ull b) {
    asm("fma.rn.f32x2 %0, %1, %2, %0;" : "+l"(d) : "l"(a), "l"(b));
}
__device__ __forceinline__ float2 unpack2(ull v) {
    float2 f; asm("mov.b64 {%0, %1}, %2;" : "=f"(f.x), "=f"(f.y) : "l"(v)); return f;
}

// ---------------------------------------------------------------------------
// K1: depthwise 3x3 conv (+bias) NCHW -> NHWC, transpose x -> NHWC,
//     per-block partial sums for GroupNorm stats.
// grid: (W/32, C/32, N*H), block: (32, 8)
// ---------------------------------------------------------------------------
__global__ __launch_bounds__(256) void k_conv(const float* __restrict__ x,
                                              const float* __restrict__ dww,
                                              const float* __restrict__ dwb) {
    int wt = blockIdx.x, ct = blockIdx.y, nh = blockIdx.z;
    int n = nh >> 6, h = nh & 63;
    int w = wt * 32 + threadIdx.x;
    int c0 = ct * 32;

    __shared__ float t1[32][33];
    __shared__ float t0[32][33];
    __shared__ float rs[256];
    __shared__ float rq[256];

    float s1 = 0.f, s2 = 0.f;

    #pragma unroll
    for (int i = 0; i < 4; i++) {
        int cl = threadIdx.y * 4 + i;
        int c = c0 + cl;
        const float* xp = x + ((size_t)(n * C_ + c) * H_) * W_;
        float wgt[9];
        #pragma unroll
        for (int k = 0; k < 9; k++) wgt[k] = dww[c * 9 + k];
        float acc = dwb[c];
        float center = 0.f;
        #pragma unroll
        for (int dy = 0; dy < 3; dy++) {
            int hy = h + dy - 1;
            if (hy < 0 || hy >= H_) continue;
            #pragma unroll
            for (int dx = 0; dx < 3; dx++) {
                int wx = w + dx - 1;
                if (wx < 0 || wx >= W_) continue;
                float v = __ldg(xp + hy * W_ + wx);
                acc = fmaf(wgt[dy * 3 + dx], v, acc);
                if (dy == 1 && dx == 1) center = v;
            }
        }
        t1[cl][threadIdx.x] = acc;
        t0[cl][threadIdx.x] = center;
        s1 += acc;
        s2 += acc * acc;
    }

    int t = threadIdx.y * 32 + threadIdx.x;
    rs[t] = s1; rq[t] = s2;
    __syncthreads();
    #pragma unroll
    for (int s = 128; s > 0; s >>= 1) {
        if (t < s) { rs[t] += rs[t + s]; rq[t] += rq[t + s]; }
        __syncthreads();
    }
    if (t == 0) {
        int pid = (h * 2 + wt) * 8 + ct;   // 1024 blocks per sample
        g_part[(n * 1024 + pid) * 2 + 0] = rs[0];
        g_part[(n * 1024 + pid) * 2 + 1] = rq[0];
    }

    // coalesced NHWC writes (thread.x now indexes channel)
    #pragma unroll
    for (int i = 0; i < 4; i++) {
        int ww = threadIdx.y + 8 * i;
        size_t pix = (size_t)(n * H_ + h) * W_ + wt * 32 + ww;
        g_x1[pix * C_ + c0 + threadIdx.x] = t1[threadIdx.x][ww];
        g_xn[pix * C_ + c0 + threadIdx.x] = t0[threadIdx.x][ww];
    }
}

// ---------------------------------------------------------------------------
// K2: finalize per-sample mean / rstd
// ---------------------------------------------------------------------------
__global__ void k_stats() {
    int n = blockIdx.x;
    int t = threadIdx.x;
    float s1 = 0.f, s2 = 0.f;
    for (int i = t; i < 1024; i += 256) {
        s1 += g_part[(n * 1024 + i) * 2 + 0];
        s2 += g_part[(n * 1024 + i) * 2 + 1];
    }
    __shared__ float rs[256];
    __shared__ float rq[256];
    rs[t] = s1; rq[t] = s2;
    __syncthreads();
    #pragma unroll
    for (int s = 128; s > 0; s >>= 1) {
        if (t < s) { rs[t] += rs[t + s]; rq[t] += rq[t + s]; }
        __syncthreads();
    }
    if (t == 0) {
        float mu = rs[0] / (float)M_;
        float var = rq[0] / (float)M_ - mu * mu;
        g_ms[n * 2 + 0] = mu;
        g_ms[n * 2 + 1] = rsqrtf(var + 1e-5f);
    }
}

// ---------------------------------------------------------------------------
// K3: fused GN + GELU + projection GEMM (FFMA2) + softmax + sampling.
// smem layout (words):
//   [0,      9216) Ys[256][36]      (phase A/B)  -> reused as Obuf[256][33]
//   [9216,  16352) O[216][33]+pad   (GEMM out; dead after precompute)
//   [16352, 25568) Wbuf4: float4[72][32]  (premult corner weights)
//   [25568, 27872) Wbufi: int[72][32]     (packed base idx + steps)
// ---------------------------------------------------------------------------
#define YS_W   9216
#define O_W    7136
#define W4_W   9216
#define WI_W   2304
#define SMEM_BYTES ((YS_W + O_W + W4_W + WI_W) * 4)

__global__ __launch_bounds__(256) void k_main(const float* __restrict__ gng,
                                              const float* __restrict__ gnb,
                                              const float* __restrict__ offw,
                                              const float* __restrict__ offb,
                                              const float* __restrict__ maskw,
                                              const float* __restrict__ maskb,
                                              float* __restrict__ out) {
    extern __shared__ __align__(16) float sm[];
    float* Ys    = sm;                       // [256][36]
    float* O     = sm + YS_W;                // [216][33]
    float* Wbuf4 = sm + YS_W + O_W;          // float4[72][32] (viewed as float)
    int*   Wbufi = (int*)(sm + YS_W + O_W + W4_W);

    int wt = blockIdx.x, h = blockIdx.y, n = blockIdx.z;
    int w0 = wt * 32;
    int t = threadIdx.x;
    int lane = t & 31;
    int wid = t >> 5;

    float mu = g_ms[n * 2 + 0];
    float rstd = g_ms[n * 2 + 1];

    // ---- Phase A: GN + GELU into Ys[c][pix] ----
    size_t pixbase = (size_t)(n * H_ + h) * W_ + w0;
    #pragma unroll
    for (int q = 0; q < 4; q++) {
        int pix = wid * 4 + q;
        const float* src = g_x1 + (pixbase + pix) * C_;
        #pragma unroll
        for (int half = 0; half < 2; half++) {
            int c = lane * 4 + half * 128;
            float4 v  = *(const float4*)(src + c);
            float4 gg = *(const float4*)(gng + c);
            float4 bb = *(const float4*)(gnb + c);
            Ys[(c + 0) * 36 + pix] = gelu_exact(fmaf((v.x - mu) * rstd, gg.x, bb.x));
            Ys[(c + 1) * 36 + pix] = gelu_exact(fmaf((v.y - mu) * rstd, gg.y, bb.y));
            Ys[(c + 2) * 36 + pix] = gelu_exact(fmaf((v.z - mu) * rstd, gg.z, bb.z));
            Ys[(c + 3) * 36 + pix] = gelu_exact(fmaf((v.w - mu) * rstd, gg.w, bb.w));
        }
    }
    __syncthreads();

    // ---- Phase B: GEMM  O[216][32] = W^T @ Ys + bias, with f32x2 FMA ----
    // thread t<216: 4 outputs (2 j-pairs in packed lanes) x 8 pixels
    if (t < 216) {
        int jt = t >> 2, pt = t & 3;
        int j0 = jt * 4;
        const float* wb;
        const float* bptr;
        int stride;
        if (j0 < 144) { wb = offw + j0; bptr = offb + j0; stride = 144; }
        else          { wb = maskw + (j0 - 144); bptr = maskb + (j0 - 144); stride = 72; }

        ull acc[16];
        {
            ull b01 = pack2(bptr[0], bptr[1]);
            ull b23 = pack2(bptr[2], bptr[3]);
            #pragma unroll
            for (int pp = 0; pp < 8; pp++) { acc[pp] = b01; acc[8 + pp] = b23; }
        }

        const float* yc = Ys + pt * 8;
        #pragma unroll 2
        for (int c = 0; c < 256; c++) {
            float4 wv = *(const float4*)(wb + (size_t)c * stride);
            ull w01 = pack2(wv.x, wv.y);
            ull w23 = pack2(wv.z, wv.w);
            float4 ya = *(const float4*)(yc);
            float4 yb = *(const float4*)(yc + 4);
            ull yd[8];
            yd[0] = dup2(ya.x); yd[1] = dup2(ya.y); yd[2] = dup2(ya.z); yd[3] = dup2(ya.w);
            yd[4] = dup2(yb.x); yd[5] = dup2(yb.y); yd[6] = dup2(yb.z); yd[7] = dup2(yb.w);
            #pragma unroll
            for (int pp = 0; pp < 8; pp++) fma2(acc[pp], w01, yd[pp]);
            #pragma unroll
            for (int pp = 0; pp < 8; pp++) fma2(acc[8 + pp], w23, yd[pp]);
            yc += 36;
        }

        #pragma unroll
        for (int jp = 0; jp < 2; jp++)
            #pragma unroll
            for (int pp = 0; pp < 8; pp++) {
                float2 f = unpack2(acc[jp * 8 + pp]);
                O[(j0 + 2 * jp + 0) * 33 + pt * 8 + pp] = f.x;
                O[(j0 + 2 * jp + 1) * 33 + pt * 8 + pp] = f.y;
            }
    }
    __syncthreads();

    // ---- Phase C1: per-warp precompute (lane = pixel) ----
    // softmax + premultiplied bilinear corner weights + packed clamped index.
    {
        int g = wid, pix = lane;
        float ml[9];
        float mx = -1e30f;
        #pragma unroll
        for (int p = 0; p < P_; p++) {
            ml[p] = O[(144 + g * P_ + p) * 33 + pix];
            mx = fmaxf(mx, ml[p]);
        }
        float s = 0.f;
        #pragma unroll
        for (int p = 0; p < P_; p++) { ml[p] = __expf(ml[p] - mx); s += ml[p]; }
        float inv = 1.f / s;

        float wpixf = (float)(w0 + pix);
        float hf = (float)h;
        #pragma unroll
        for (int p = 0; p < P_; p++) {
            float ox = O[((g * P_ + p) * 2 + 0) * 33 + pix];
            float oy = O[((g * P_ + p) * 2 + 1) * 33 + pix];
            float fx = wpixf + (float)(p / 3 - 1) + ox;
            float fy = hf    + (float)(p % 3 - 1) + oy;
            fx = fminf(fmaxf(fx, -2.f), (float)(W_ + 1));
            fy = fminf(fmaxf(fy, -2.f), (float)(H_ + 1));
            float x0f = floorf(fx), y0f = floorf(fy);
            float wxf = fx - x0f, wyf = fy - y0f;
            int ix = (int)x0f, iy = (int)y0f;
            float m = ml[p] * inv;
            float ax0 = (ix >= 0 && ix < W_)          ? (1.f - wxf) : 0.f;
            float ax1 = (ix + 1 >= 0 && ix + 1 < W_)  ? wxf         : 0.f;
            float ay0 = (iy >= 0 && iy < H_)          ? (1.f - wyf) : 0.f;
            float ay1 = (iy + 1 >= 0 && iy + 1 < H_)  ? wyf         : 0.f;
            float4 wv;
            wv.x = m * ay0 * ax0;
            wv.y = m * ay0 * ax1;
            wv.z = m * ay1 * ax0;
            wv.w = m * ay1 * ax1;
            int ix0c = min(max(ix, 0), W_ - 1);
            int iy0c = min(max(iy, 0), H_ - 1);
            int dx   = min(max(ix + 1, 0), W_ - 1) - ix0c;   // 0 or 1
            int dy   = min(max(iy + 1, 0), H_ - 1) - iy0c;   // 0 or 1
            int off  = iy0c * W_ + ix0c;                      // 0..4095
            int idx = (g * P_ + p) * 32 + pix;
            *(float4*)(Wbuf4 + 4 * idx) = wv;
            Wbufi[idx] = off | (dx << 12) | (dy << 13);
        }
    }
    __syncwarp();   // each warp consumes only its own precomputed data

    // ---- Phase C2: gather. lanes span the 32 group channels ----
    float* Obuf = Ys;   // Ys dead; [256][33]
    {
        int g = wid;
        const float* xb = g_xn + (size_t)n * HW_ * C_ + g * CG_ + lane;
        for (int pix = 0; pix < 32; pix++) {
            float acc = 0.f;
            #pragma unroll
            for (int p = 0; p < P_; p++) {
                int idx = (g * P_ + p) * 32 + pix;
                float4 wv = *(const float4*)(Wbuf4 + 4 * idx);
                int v = Wbufi[idx];
                int off  = v & 0xFFF;
                int dxo  = ((v >> 12) & 1) * C_;
                int dyo  = ((v >> 13) & 1) * (W_ * C_);
                const float* rp = xb + (size_t)off * C_;
                acc = fmaf(wv.x, __ldg(rp), acc);
                acc = fmaf(wv.y, __ldg(rp + dxo), acc);
                acc = fmaf(wv.z, __ldg(rp + dyo), acc);
                acc = fmaf(wv.w, __ldg(rp + dyo + dxo), acc);
            }
            Obuf[(g * CG_ + lane) * 33 + pix] = acc;
        }
    }
    __syncthreads();

    // ---- Phase D: coalesced NCHW store ----
    #pragma unroll
    for (int i = 0; i < 32; i++) {
        int c = wid * 32 + i;
        out[((size_t)(n * C_ + c) * H_ + h) * W_ + w0 + lane] = Obuf[c * 33 + lane];
    }
}

// ---------------------------------------------------------------------------
extern "C" void kernel_launch(void* const* d_in, const int* in_sizes, int n_in,
                              void* d_out, int out_size) {
    const float* x     = (const float*)d_in[0];
    const float* dw_w  = (const float*)d_in[1];
    const float* dw_b  = (const float*)d_in[2];
    const float* gn_g  = (const float*)d_in[3];
    const float* gn_b  = (const float*)d_in[4];
    const float* off_w = (const float*)d_in[5];
    const float* off_b = (const float*)d_in[6];
    const float* mask_w= (const float*)d_in[7];
    const float* mask_b= (const float*)d_in[8];
    float* out = (float*)d_out;

    cudaFuncSetAttribute(k_main, cudaFuncAttributeMaxDynamicSharedMemorySize, SMEM_BYTES);

    dim3 g1(W_ / 32, C_ / 32, NB * H_);
    dim3 b1(32, 8);
    k_conv<<<g1, b1>>>(x, dw_w, dw_b);
    k_stats<<<NB, 256>>>();
    dim3 g3(W_ / 32, H_, NB);
    k_main<<<g3, 256, SMEM_BYTES>>>(gn_g, gn_b, off_w, off_b, mask_w, mask_b, out);
}